// round 7
// baseline (speedup 1.0000x reference)
#include <cuda_runtime.h>

// SEIR scan — single kernel, block-specialized producer/consumer overlap.
// Output layout: [4, T, B] — planes S, E, I, R.
//
// Producer blocks (0..63, 128 active threads): serial scan over T, publish
//   chunk-boundary states every STEP=16 steps + per-chunk release counters.
// Consumer blocks (64..447, 256 threads): statically staggered (chunk, group)
//   tasks; ONE thread per block polls the chunk counter (128B-padded, so only
//   a handful of pollers per address); recompute 16 rows, float4 evict-first
//   stores.

#define STEP   16
#define RING   32
#define MAXB   8192
#define MAXC   256              // supports T up to 4096
#define NPRODB 64
#define NCONSB 384
#define PROD_WARPS 256          // 64 blocks x 4 warps

__device__ float g_bS[MAXC * MAXB];
__device__ float g_bE[MAXC * MAXB];
__device__ float g_bI[MAXC * MAXB];
__device__ float g_bR[MAXC * MAXB];
__device__ unsigned g_cnt[MAXC * 32];   // per-chunk counters, 128B stride

__device__ __forceinline__ unsigned ld_acq(const unsigned* p)
{
    unsigned v;
    asm volatile("ld.acquire.gpu.global.u32 %0, [%1];"
                 : "=r"(v) : "l"(p) : "memory");
    return v;
}

// one SEIR step, fma form; invN folded into wbN.
__device__ __forceinline__ void seir_step2(float x, float wbN, float wg, float ws,
                                           float& S, float& E, float& I, float& R)
{
    const float bN = x * wbN;
    const float s2 = x * ws;
    const float g3 = x * wg;
    const float eD = 1.0f - s2;
    const float iD = 1.0f - g3;
    const float v    = bN * I;
    const float StoE = v * S;
    const float EtoI = s2 * E;
    const float Sn = fmaf(-v, S, S);
    const float En = fmaf(E, eD, StoE);
    const float In = fmaf(I, iD, EtoI);
    const float Rn = fmaf(g3, I, R);
    S = Sn; E = En; I = In; R = Rn;
}

template<int B_>
__device__ __forceinline__ void publish(int c, int b, int lane,
                                        float S, float E, float I, float R)
{
    const int idx = c * B_ + b;
    g_bS[idx] = S; g_bE[idx] = E; g_bI[idx] = I; g_bR[idx] = R;
    __threadfence();
    __syncwarp();
    if (lane == 0) atomicAdd(&g_cnt[c * 32], 1u);
}

template<int B_>
__global__ __launch_bounds__(256, 3)
void seir_overlap(const float* __restrict__ X,
                  const float* __restrict__ w_beta,
                  const float* __restrict__ w_gamma,
                  const float* __restrict__ w_sigma,
                  const float* __restrict__ S0,
                  const float* __restrict__ I0,
                  const float* __restrict__ R0,
                  const float* __restrict__ Nvec,
                  float* __restrict__ out,
                  int T, int chunks)
{
    const int tid  = threadIdx.x;
    const int lane = tid & 31;

    // ============================================================ producer
    if (blockIdx.x < NPRODB) {
        if (tid >= 128) return;               // no __syncthreads in this path
        const int b = blockIdx.x * 128 + tid;

        const float invN = 1.0f / Nvec[b];
        const float wbN  = w_beta[b] * invN;
        const float wg   = w_gamma[b];
        const float ws   = w_sigma[b];

        float S = S0[b];
        float E = 0.0f;
        float I = I0[b];
        float R = R0[b];

        const int NS = (chunks - 1) * STEP;
        if (NS <= 0) return;

        const float* __restrict__ xp = X + b;

        float xr[RING];
#pragma unroll
        for (int k = 0; k < RING; ++k)
            xr[k] = (k < NS) ? xp[(size_t)k * B_] : 0.0f;

        int base = 0;
        // main: unpredicated prefetch (immediate offsets; B_ is constexpr)
        for (; base + 2 * RING <= NS; base += RING) {
            const float* __restrict__ pf = xp + (size_t)(base + RING) * B_;
#pragma unroll
            for (int k = 0; k < RING; ++k) {
                const float x = xr[k];
                xr[k] = pf[(size_t)k * B_];
                seir_step2(x, wbN, wg, ws, S, E, I, R);
                if (((k + 1) & (STEP - 1)) == 0)      // static: k = 15, 31
                    publish<B_>((base + k + 1) / STEP, b, lane, S, E, I, R);
            }
        }
        // predicated tail
        for (; base < NS; base += RING) {
#pragma unroll
            for (int k = 0; k < RING; ++k) {
                const int t = base + k;
                if (t < NS) {
                    const float x = xr[k];
                    const int tn = t + RING;
                    xr[k] = (tn < NS) ? xp[(size_t)tn * B_] : 0.0f;
                    seir_step2(x, wbN, wg, ws, S, E, I, R);
                    if (((t + 1) & (STEP - 1)) == 0)
                        publish<B_>((t + 1) / STEP, b, lane, S, E, I, R);
                }
            }
        }
        return;
    }

    // ============================================================ consumer
    const int q = blockIdx.x - NPRODB;        // 0 .. NCONSB-1
    const int ntasks = chunks * 8;            // 8 groups of 1024 channels

    const size_t TB = (size_t)T * (size_t)B_;
    float* __restrict__ oS = out;
    float* __restrict__ oE = out + TB;
    float* __restrict__ oI = out + 2 * TB;
    float* __restrict__ oR = out + 3 * TB;

    for (int tau = q; tau < ntasks; tau += NCONSB) {
        const int c = tau >> 3;
        const int g = tau & 7;
        const int b = g * 1024 + tid * 4;

        // wait for the chunk-c boundary (chunk 0 reads the inputs directly)
        if (c > 0) {
            if (tid == 0) {
                while (ld_acq(&g_cnt[c * 32]) < PROD_WARPS)
                    __nanosleep(128);
            }
            __syncthreads();
            __threadfence();
        }

        const int t0  = c * STEP;
        const int nst = min(STEP, T - t0) - 1;

        const float4 wb = *(const float4*)(w_beta  + b);
        const float4 wg = *(const float4*)(w_gamma + b);
        const float4 ws = *(const float4*)(w_sigma + b);
        const float4 nv = *(const float4*)(Nvec    + b);
        const float4 wbN = make_float4(wb.x / nv.x, wb.y / nv.y,
                                       wb.z / nv.z, wb.w / nv.w);

        float4 S, E, I, R;
        if (c == 0) {
            S = *(const float4*)(S0 + b);
            E = make_float4(0.f, 0.f, 0.f, 0.f);
            I = *(const float4*)(I0 + b);
            R = *(const float4*)(R0 + b);
        } else {
            const int bi = c * B_ + b;
            S = __ldcg((const float4*)(g_bS + bi));
            E = __ldcg((const float4*)(g_bE + bi));
            I = __ldcg((const float4*)(g_bI + bi));
            R = __ldcg((const float4*)(g_bR + bi));
        }

        size_t r = (size_t)t0 * B_ + b;
        __stcs((float4*)(oS + r), S);
        __stcs((float4*)(oE + r), E);
        __stcs((float4*)(oI + r), I);
        __stcs((float4*)(oR + r), R);

        const float* __restrict__ xp = X + (size_t)t0 * B_ + b;
        float4 xn = (nst > 0) ? *(const float4*)xp
                              : make_float4(0.f, 0.f, 0.f, 0.f);

        if (nst == STEP - 1) {
#pragma unroll
            for (int i = 0; i < STEP - 1; ++i) {
                const float4 x = xn;
                if (i + 1 < STEP - 1)
                    xn = *(const float4*)(xp + (size_t)(i + 1) * B_);
                seir_step2(x.x, wbN.x, wg.x, ws.x, S.x, E.x, I.x, R.x);
                seir_step2(x.y, wbN.y, wg.y, ws.y, S.y, E.y, I.y, R.y);
                seir_step2(x.z, wbN.z, wg.z, ws.z, S.z, E.z, I.z, R.z);
                seir_step2(x.w, wbN.w, wg.w, ws.w, S.w, E.w, I.w, R.w);
                r += B_;
                __stcs((float4*)(oS + r), S);
                __stcs((float4*)(oE + r), E);
                __stcs((float4*)(oI + r), I);
                __stcs((float4*)(oR + r), R);
            }
        } else {
            for (int i = 0; i < nst; ++i) {
                const float4 x = xn;
                if (i + 1 < nst)
                    xn = *(const float4*)(xp + (size_t)(i + 1) * B_);
                seir_step2(x.x, wbN.x, wg.x, ws.x, S.x, E.x, I.x, R.x);
                seir_step2(x.y, wbN.y, wg.y, ws.y, S.y, E.y, I.y, R.y);
                seir_step2(x.z, wbN.z, wg.z, ws.z, S.z, E.z, I.z, R.z);
                seir_step2(x.w, wbN.w, wg.w, ws.w, S.w, E.w, I.w, R.w);
                r += B_;
                __stcs((float4*)(oS + r), S);
                __stcs((float4*)(oE + r), E);
                __stcs((float4*)(oI + r), I);
                __stcs((float4*)(oR + r), R);
            }
        }
    }
}

// ------------------------------------------------ fallback (shape safety)
__global__ void seir_fallback(const float* __restrict__ X,
                              const float* __restrict__ w_beta,
                              const float* __restrict__ w_gamma,
                              const float* __restrict__ w_sigma,
                              const float* __restrict__ S0,
                              const float* __restrict__ I0,
                              const float* __restrict__ R0,
                              const float* __restrict__ Nvec,
                              float* __restrict__ out, int T, int B)
{
    const int b = blockIdx.x * blockDim.x + threadIdx.x;
    if (b >= B) return;
    const float invN = 1.0f / Nvec[b];
    const float wbN = w_beta[b] * invN;
    const float wg = w_gamma[b], ws = w_sigma[b];
    float S = S0[b], E = 0.0f, I = I0[b], R = R0[b];
    const size_t TB = (size_t)T * B;
    out[b] = S; out[TB + b] = E; out[2 * TB + b] = I; out[3 * TB + b] = R;
    for (int t = 0; t < T - 1; ++t) {
        const float x = X[(size_t)t * B + b];
        seir_step2(x, wbN, wg, ws, S, E, I, R);
        const size_t r = (size_t)(t + 1) * B + b;
        out[r] = S; out[TB + r] = E; out[2 * TB + r] = I; out[3 * TB + r] = R;
    }
}

extern "C" void kernel_launch(void* const* d_in, const int* in_sizes, int n_in,
                              void* d_out, int out_size)
{
    const float* X      = (const float*)d_in[0];
    const float* w_beta = (const float*)d_in[1];
    const float* w_gamma= (const float*)d_in[2];
    const float* w_sigma= (const float*)d_in[3];
    const float* S0     = (const float*)d_in[4];
    const float* I0     = (const float*)d_in[5];
    const float* R0     = (const float*)d_in[6];
    const float* Nvec   = (const float*)d_in[7];
    float* out = (float*)d_out;

    const int B = in_sizes[1];         // w_beta is [B]
    const int T = in_sizes[0] / B;     // X is [T, B]
    const int chunks = (T + STEP - 1) / STEP;

    if (B == 8192 && chunks <= MAXC && T >= 2) {
        void* cnt_addr = nullptr;
        cudaGetSymbolAddress(&cnt_addr, g_cnt);
        cudaMemsetAsync(cnt_addr, 0, sizeof(unsigned) * MAXC * 32, 0);

        seir_overlap<8192><<<NPRODB + NCONSB, 256>>>(X, w_beta, w_gamma,
                                                     w_sigma, S0, I0, R0,
                                                     Nvec, out, T, chunks);
    } else {
        seir_fallback<<<(B + 127) / 128, 128>>>(X, w_beta, w_gamma, w_sigma,
                                                S0, I0, R0, Nvec, out, T, B);
    }
}

// round 8
// speedup vs baseline: 1.6417x; 1.6417x over previous
#include <cuda_runtime.h>

// SEIR scan, two-pass chunked recomputation.
// Output layout: [4, T, B] — planes S, E, I, R.
//
// Pass 1: one thread per channel, serial scan; step arithmetic packed with
//         f32x2 (sm_103a FFMA2/FMUL2) to halve fma-pipe issue count.
// Pass 2: (chunk, channel/4) grid, recomputes 16-step chunks, float4
//         evict-first stores. (Unchanged from the 55.9us version.)

#define STEP   16
#define RING   32
#define MAXB   8192
#define MAXC   256   // supports T up to 4096

__device__ float g_bS[MAXC * MAXB];
__device__ float g_bE[MAXC * MAXB];
__device__ float g_bI[MAXC * MAXB];
__device__ float g_bR[MAXC * MAXB];

// ---- packed f32x2 helpers (sm_103a) ----
__device__ __forceinline__ unsigned long long pk2(float lo, float hi)
{
    unsigned long long r;
    asm("mov.b64 %0, {%1, %2};" : "=l"(r) : "f"(lo), "f"(hi));
    return r;
}
__device__ __forceinline__ void upk2(unsigned long long v, float& lo, float& hi)
{
    asm("mov.b64 {%0, %1}, %2;" : "=f"(lo), "=f"(hi) : "l"(v));
}
__device__ __forceinline__ unsigned long long mul2(unsigned long long a,
                                                   unsigned long long b)
{
    unsigned long long r;
    asm("mul.rn.f32x2 %0, %1, %2;" : "=l"(r) : "l"(a), "l"(b));
    return r;
}
__device__ __forceinline__ unsigned long long fma2(unsigned long long a,
                                                   unsigned long long b,
                                                   unsigned long long c)
{
    unsigned long long r;
    asm("fma.rn.f32x2 %0, %1, %2, %3;" : "=l"(r) : "l"(a), "l"(b), "l"(c));
    return r;
}

// scalar SEIR step (pass2 / fallback); invN folded into wbN.
__device__ __forceinline__ void seir_step2(float x, float wbN, float wg, float ws,
                                           float& S, float& E, float& I, float& R)
{
    const float bN = x * wbN;
    const float s2 = x * ws;
    const float g3 = x * wg;
    const float eD = 1.0f - s2;
    const float iD = 1.0f - g3;
    const float v    = bN * I;
    const float StoE = v * S;
    const float EtoI = s2 * E;
    const float Sn = fmaf(-v, S, S);
    const float En = fmaf(E, eD, StoE);
    const float In = fmaf(I, iD, EtoI);
    const float Rn = fmaf(g3, I, R);
    S = Sn; E = En; I = In; R = Rn;
}

// packed SEIR step for pass1: state EI = (E, I) packed, S/R scalar.
// WSG = (ws, wg), NWSG = (-ws, -wg), ONES = (1, 1).
// E' = E*(1-x*ws) + StoE ; I' = I*(1-x*wg) + EtoI  (identical algebra to
// seir_step2, so pass1/pass2 boundary states agree bit-for-bit).
__device__ __forceinline__ void seir_step_pk(float x, float wbN,
                                             unsigned long long WSG,
                                             unsigned long long NWSG,
                                             unsigned long long ONES,
                                             float& S, unsigned long long& EI,
                                             float& R)
{
    const unsigned long long x2 = pk2(x, x);
    const unsigned long long SG = mul2(x2, WSG);         // (s2, g3)
    const unsigned long long ED = fma2(x2, NWSG, ONES);  // (1-s2, 1-g3)
    float E, I;  upk2(EI, E, I);
    const float bN   = x * wbN;
    const float v    = bN * I;
    const float StoE = v * S;
    const unsigned long long M = mul2(SG, EI);           // (EtoI, ItoR)
    float EtoI, ItoR;  upk2(M, EtoI, ItoR);
    EI = fma2(EI, ED, pk2(StoE, EtoI));
    S  = S - StoE;
    R  = R + ItoR;
}

// ---------------------------------------------------------------- pass 1
template<int B_>
__global__ __launch_bounds__(64, 1)
void seir_pass1(const float* __restrict__ X,
                const float* __restrict__ w_beta,
                const float* __restrict__ w_gamma,
                const float* __restrict__ w_sigma,
                const float* __restrict__ S0,
                const float* __restrict__ I0,
                const float* __restrict__ R0,
                const float* __restrict__ Nvec,
                int NS)   // (chunks-1)*STEP serial steps
{
    const int b = blockIdx.x * 64 + threadIdx.x;

    const float invN = 1.0f / Nvec[b];
    const float wbN  = w_beta[b] * invN;
    const float wg   = w_gamma[b];
    const float ws   = w_sigma[b];

    const unsigned long long WSG  = pk2(ws, wg);
    const unsigned long long NWSG = pk2(-ws, -wg);
    const unsigned long long ONES = pk2(1.0f, 1.0f);

    float S = S0[b];
    float R = R0[b];
    unsigned long long EI = pk2(0.0f, I0[b]);   // (E, I)

    // boundary 0 = initial state
    {
        float E, I; upk2(EI, E, I);
        g_bS[b] = S; g_bE[b] = E; g_bI[b] = I; g_bR[b] = R;
    }
    if (NS <= 0) return;

    const float* __restrict__ xp = X + b;

    float xr[RING];
#pragma unroll
    for (int k = 0; k < RING; ++k)
        xr[k] = (k < NS) ? xp[(size_t)k * B_] : 0.0f;

    int base = 0;
    // main: unpredicated prefetch of the next full ring (immediate offsets)
    for (; base + 2 * RING <= NS; base += RING) {
        const float* __restrict__ pf = xp + (size_t)(base + RING) * B_;
#pragma unroll
        for (int k = 0; k < RING; ++k) {
            const float x = xr[k];
            xr[k] = pf[(size_t)k * B_];
            seir_step_pk(x, wbN, WSG, NWSG, ONES, S, EI, R);
            if (((k + 1) & (STEP - 1)) == 0) {       // static: k = 15, 31
                const int c   = (base + k + 1) / STEP;
                const int idx = c * B_ + b;
                float E, I; upk2(EI, E, I);
                g_bS[idx] = S; g_bE[idx] = E; g_bI[idx] = I; g_bR[idx] = R;
            }
        }
    }
    // predicated tail
    for (; base < NS; base += RING) {
#pragma unroll
        for (int k = 0; k < RING; ++k) {
            const int t = base + k;
            if (t < NS) {
                const float x = xr[k];
                const int tn = t + RING;
                xr[k] = (tn < NS) ? xp[(size_t)tn * B_] : 0.0f;
                seir_step_pk(x, wbN, WSG, NWSG, ONES, S, EI, R);
                if (((t + 1) & (STEP - 1)) == 0) {
                    const int c   = (t + 1) / STEP;
                    const int idx = c * B_ + b;
                    float E, I; upk2(EI, E, I);
                    g_bS[idx] = S; g_bE[idx] = E; g_bI[idx] = I; g_bR[idx] = R;
                }
            }
        }
    }
}

// ---------------------------------------------------------------- pass 2
__global__ __launch_bounds__(256)
void seir_pass2(const float* __restrict__ X,
                const float* __restrict__ w_beta,
                const float* __restrict__ w_gamma,
                const float* __restrict__ w_sigma,
                const float* __restrict__ Nvec,
                float* __restrict__ out,
                int T, int B)
{
    const int j = blockIdx.x * blockDim.x + threadIdx.x;   // channel/4
    const int b = j * 4;
    if (b >= B) return;

    const int c  = blockIdx.y;
    const int t0 = c * STEP;
    if (t0 >= T) return;
    const int tend = min(t0 + STEP, T);
    const int nst  = tend - t0 - 1;

    const float4 wb = *(const float4*)(w_beta  + b);
    const float4 wg = *(const float4*)(w_gamma + b);
    const float4 ws = *(const float4*)(w_sigma + b);
    const float4 nv = *(const float4*)(Nvec    + b);
    const float4 wbN = make_float4(wb.x / nv.x, wb.y / nv.y,
                                   wb.z / nv.z, wb.w / nv.w);

    const int bi = c * B + b;
    float4 S = *(const float4*)(g_bS + bi);
    float4 E = *(const float4*)(g_bE + bi);
    float4 I = *(const float4*)(g_bI + bi);
    float4 R = *(const float4*)(g_bR + bi);

    const size_t TB = (size_t)T * (size_t)B;
    float* __restrict__ oS = out;
    float* __restrict__ oE = out + TB;
    float* __restrict__ oI = out + 2 * TB;
    float* __restrict__ oR = out + 3 * TB;

    size_t r = (size_t)t0 * B + b;
    __stcs((float4*)(oS + r), S);
    __stcs((float4*)(oE + r), E);
    __stcs((float4*)(oI + r), I);
    __stcs((float4*)(oR + r), R);

    const float* __restrict__ xp = X + (size_t)t0 * B + b;
    float4 xn = (nst > 0) ? *(const float4*)xp : make_float4(0.f, 0.f, 0.f, 0.f);

    if (nst == STEP - 1) {
#pragma unroll
        for (int i = 0; i < STEP - 1; ++i) {
            const float4 x = xn;
            if (i + 1 < STEP - 1)
                xn = *(const float4*)(xp + (i + 1) * B);
            seir_step2(x.x, wbN.x, wg.x, ws.x, S.x, E.x, I.x, R.x);
            seir_step2(x.y, wbN.y, wg.y, ws.y, S.y, E.y, I.y, R.y);
            seir_step2(x.z, wbN.z, wg.z, ws.z, S.z, E.z, I.z, R.z);
            seir_step2(x.w, wbN.w, wg.w, ws.w, S.w, E.w, I.w, R.w);
            r += B;
            __stcs((float4*)(oS + r), S);
            __stcs((float4*)(oE + r), E);
            __stcs((float4*)(oI + r), I);
            __stcs((float4*)(oR + r), R);
        }
    } else {
        for (int i = 0; i < nst; ++i) {
            const float4 x = xn;
            if (i + 1 < nst)
                xn = *(const float4*)(xp + (i + 1) * B);
            seir_step2(x.x, wbN.x, wg.x, ws.x, S.x, E.x, I.x, R.x);
            seir_step2(x.y, wbN.y, wg.y, ws.y, S.y, E.y, I.y, R.y);
            seir_step2(x.z, wbN.z, wg.z, ws.z, S.z, E.z, I.z, R.z);
            seir_step2(x.w, wbN.w, wg.w, ws.w, S.w, E.w, I.w, R.w);
            r += B;
            __stcs((float4*)(oS + r), S);
            __stcs((float4*)(oE + r), E);
            __stcs((float4*)(oI + r), I);
            __stcs((float4*)(oR + r), R);
        }
    }
}

// ------------------------------------------------ fallback (shape safety)
__global__ void seir_fallback(const float* __restrict__ X,
                              const float* __restrict__ w_beta,
                              const float* __restrict__ w_gamma,
                              const float* __restrict__ w_sigma,
                              const float* __restrict__ S0,
                              const float* __restrict__ I0,
                              const float* __restrict__ R0,
                              const float* __restrict__ Nvec,
                              float* __restrict__ out, int T, int B)
{
    const int b = blockIdx.x * blockDim.x + threadIdx.x;
    if (b >= B) return;
    const float invN = 1.0f / Nvec[b];
    const float wbN = w_beta[b] * invN;
    const float wg = w_gamma[b], ws = w_sigma[b];
    float S = S0[b], E = 0.0f, I = I0[b], R = R0[b];
    const size_t TB = (size_t)T * B;
    out[b] = S; out[TB + b] = E; out[2 * TB + b] = I; out[3 * TB + b] = R;
    for (int t = 0; t < T - 1; ++t) {
        const float x = X[(size_t)t * B + b];
        seir_step2(x, wbN, wg, ws, S, E, I, R);
        const size_t r = (size_t)(t + 1) * B + b;
        out[r] = S; out[TB + r] = E; out[2 * TB + r] = I; out[3 * TB + r] = R;
    }
}

extern "C" void kernel_launch(void* const* d_in, const int* in_sizes, int n_in,
                              void* d_out, int out_size)
{
    const float* X      = (const float*)d_in[0];
    const float* w_beta = (const float*)d_in[1];
    const float* w_gamma= (const float*)d_in[2];
    const float* w_sigma= (const float*)d_in[3];
    const float* S0     = (const float*)d_in[4];
    const float* I0     = (const float*)d_in[5];
    const float* R0     = (const float*)d_in[6];
    const float* Nvec   = (const float*)d_in[7];
    float* out = (float*)d_out;

    const int B = in_sizes[1];         // w_beta is [B]
    const int T = in_sizes[0] / B;     // X is [T, B]
    const int chunks = (T + STEP - 1) / STEP;

    if (B == 8192 && chunks <= MAXC && T >= 2) {
        const int NS = (chunks - 1) * STEP;
        seir_pass1<8192><<<8192 / 64, 64>>>(X, w_beta, w_gamma, w_sigma,
                                            S0, I0, R0, Nvec, NS);
        dim3 g2(8192 / 4 / 256, chunks);
        seir_pass2<<<g2, 256>>>(X, w_beta, w_gamma, w_sigma, Nvec,
                                out, T, B);
    } else {
        seir_fallback<<<(B + 127) / 128, 128>>>(X, w_beta, w_gamma, w_sigma,
                                                S0, I0, R0, Nvec, out, T, B);
    }
}